// round 12
// baseline (speedup 1.0000x reference)
#include <cuda_runtime.h>

#define HH 256
#define WW 256
#define NI 16
#define CC 3
#define HW (HH * WW)

__device__ __forceinline__ void stcs(float* p, float v) {
#if __CUDA_ARCH__ >= 800
    __stcs(p, v);
#else
    *p = v;
#endif
}

struct TapIW { int i00, i10, i01, i11; float w00, w10, w01, w11; };

__device__ __forceinline__ TapIW tap_iw(float ix, float iy, float coef) {
    TapIW t;
    const int x0 = __float2int_rd(ix);
    const int y0 = __float2int_rd(iy);
    const float wx1 = ix - (float)x0;
    const float wy1 = iy - (float)y0;
    const float wx0 = 1.0f - wx1;
    const float wy0 = 1.0f - wy1;
    const int x1 = x0 + 1, y1 = y0 + 1;
    const bool vx0 = (x0 >= 0) & (x0 < WW);
    const bool vx1 = (x1 >= 0) & (x1 < WW);
    const bool vy0 = (y0 >= 0) & (y0 < HH);
    const bool vy1 = (y1 >= 0) & (y1 < HH);
    const int x0c = min(max(x0, 0), WW - 1);
    const int x1c = min(max(x1, 0), WW - 1);
    const int y0c = min(max(y0, 0), HH - 1);
    const int y1c = min(max(y1, 0), HH - 1);
    const float wy0c = wy0 * coef;
    const float wy1c = wy1 * coef;
    t.w00 = wx0 * wy0c * ((vx0 & vy0) ? 1.0f : 0.0f);
    t.w10 = wx1 * wy0c * ((vx1 & vy0) ? 1.0f : 0.0f);
    t.w01 = wx0 * wy1c * ((vx0 & vy1) ? 1.0f : 0.0f);
    t.w11 = wx1 * wy1c * ((vx1 & vy1) ? 1.0f : 0.0f);
    t.i00 = y0c * WW + x0c;
    t.i10 = y0c * WW + x1c;
    t.i01 = y1c * WW + x0c;
    t.i11 = y1c * WW + x1c;
    return t;
}

__global__ __launch_bounds__(256, 4)
void warp_renderer_kernel(
    const float* __restrict__ g0,           // [B,NI,C,H,W]
    const float* __restrict__ m0,           // [B,NI,1,H,W]
    const float* __restrict__ mode_logits,  // [B,NI,5]
    const float* __restrict__ tp,           // [B,NI,6]
    const float* __restrict__ alpha,        // [B,NI,1]
    const float* __restrict__ inst_valid,   // [B,NI]
    const float* __restrict__ i_bg,         // [B,C,H,W]
    float* __restrict__ out,
    int B)
{
    __shared__ int   s_nact, s_ninact;
    __shared__ int   s_act_ni[NI];
    __shared__ float s_act_coef[NI];
    __shared__ float s_act_t0[NI], s_act_t3[NI];
    __shared__ float s_act_bx[NI], s_act_by[NI];
    __shared__ int   s_inact_ni[NI];

    const int b = blockIdx.x >> 8;        // blockIdx.x = b*H + y
    const int y = blockIdx.x & 255;
    const int x = threadIdx.x;

    // --- per-instance precompute + active compaction (lanes 0..15 of warp 0) ---
    if (threadIdx.x < NI) {
        const int lane = threadIdx.x;
        const int inst = b * NI + lane;
        const float* L = mode_logits + inst * 5;
        int mode = 0;
        float best = L[0];
        #pragma unroll
        for (int k = 1; k < 5; ++k) {
            float v = L[k];
            if (v > best) { best = v; mode = k; }  // first-max argmax
        }
        float coef;
        if (mode == 0 || mode == 2 || mode == 4) coef = 1.0f;       // static-like
        else if (mode == 3)                      coef = alpha[inst]; // blink
        else                                     coef = 0.0f;        // mode 1
        coef *= inst_valid[inst];

        const bool active = (coef != 0.0f);
        const unsigned mask = __ballot_sync(0x0000FFFFu, active);
        const unsigned lower = (1u << lane) - 1u;

        if (active) {
            const int pos = __popc(mask & lower);
            const float t0 = tp[inst * 6 + 0];
            const float t1 = tp[inst * 6 + 1];
            const float t2 = tp[inst * 6 + 2];
            const float t3 = tp[inst * 6 + 3];
            const float t4 = tp[inst * 6 + 4];
            const float t5 = tp[inst * 6 + 5];
            const float ys = (2.0f * (float)y + 1.0f) * (1.0f / (float)HH) - 1.0f;
            // ix = t0*x + bx ; iy = t3*x + by   (full chain folded)
            const float bx = 128.0f * (t1 * ys + t2) + 127.5f + 0.5f * t0 - 128.0f * t0;
            const float by = 128.0f * (t4 * ys + t5) + 127.5f + 0.5f * t3 - 128.0f * t3;
            s_act_ni[pos]   = lane;
            s_act_coef[pos] = coef;
            s_act_t0[pos]   = t0;
            s_act_t3[pos]   = t3;
            s_act_bx[pos]   = bx;
            s_act_by[pos]   = by;
        } else {
            const int pos = __popc((~mask) & 0xFFFFu & lower);
            s_inact_ni[pos] = lane;
        }
        if (lane == 0) {
            s_nact   = __popc(mask);
            s_ninact = NI - __popc(mask);
        }
    }
    __syncthreads();

    const int pix = y * WW + x;
    const float xf = (float)x;

    const int n_gpi = B * NI * CC * HW;
    const int n_mpi = B * NI * HW;
    float* __restrict__ out_gpi  = out;
    float* __restrict__ out_mpi  = out + n_gpi;
    float* __restrict__ out_gmid = out + n_gpi + n_mpi;
    float* __restrict__ out_mmid = out_gmid + B * CC * HW;
    float* __restrict__ out_ibas = out_mmid + B * HW;

    // --- zero stores for inactive instances (streaming) ---
    const int ninact = s_ninact;
    for (int k = 0; k < ninact; ++k) {
        const int ni = s_inact_ni[k];
        const int bgi = (b * NI + ni) * CC * HW + pix;
        const int bmi = (b * NI + ni) * HW + pix;
        stcs(out_gpi + bgi,          0.0f);
        stcs(out_gpi + bgi + HW,     0.0f);
        stcs(out_gpi + bgi + 2 * HW, 0.0f);
        stcs(out_mpi + bmi,          0.0f);
    }

    float gacc0 = 0.0f, gacc1 = 0.0f, gacc2 = 0.0f, macc = 0.0f;

    const int nact = s_nact;
    int j = 0;

    // --- paired hot loop: 2 instances, 32 loads in flight ---
    for (; j + 2 <= nact; j += 2) {
        const int base_gA = (b * NI + s_act_ni[j])     * CC * HW;
        const int base_gB = (b * NI + s_act_ni[j + 1]) * CC * HW;
        const int base_mA = (b * NI + s_act_ni[j])     * HW;
        const int base_mB = (b * NI + s_act_ni[j + 1]) * HW;

        const TapIW tA = tap_iw(fmaf(s_act_t0[j],     xf, s_act_bx[j]),
                                fmaf(s_act_t3[j],     xf, s_act_by[j]),
                                s_act_coef[j]);
        const TapIW tB = tap_iw(fmaf(s_act_t0[j + 1], xf, s_act_bx[j + 1]),
                                fmaf(s_act_t3[j + 1], xf, s_act_by[j + 1]),
                                s_act_coef[j + 1]);

        const float* __restrict__ A0 = g0 + base_gA;
        const float* __restrict__ A1 = A0 + HW;
        const float* __restrict__ A2 = A1 + HW;
        const float* __restrict__ Am = m0 + base_mA;
        const float* __restrict__ B0 = g0 + base_gB;
        const float* __restrict__ B1 = B0 + HW;
        const float* __restrict__ B2 = B1 + HW;
        const float* __restrict__ Bm = m0 + base_mB;

        // 32 independent loads
        const float a00 = __ldg(A0 + tA.i00), a10 = __ldg(A0 + tA.i10),
                    a01 = __ldg(A0 + tA.i01), a11 = __ldg(A0 + tA.i11);
        const float b00 = __ldg(A1 + tA.i00), b10 = __ldg(A1 + tA.i10),
                    b01 = __ldg(A1 + tA.i01), b11 = __ldg(A1 + tA.i11);
        const float c00 = __ldg(A2 + tA.i00), c10 = __ldg(A2 + tA.i10),
                    c01 = __ldg(A2 + tA.i01), c11 = __ldg(A2 + tA.i11);
        const float d00 = __ldg(Am + tA.i00), d10 = __ldg(Am + tA.i10),
                    d01 = __ldg(Am + tA.i01), d11 = __ldg(Am + tA.i11);
        const float e00 = __ldg(B0 + tB.i00), e10 = __ldg(B0 + tB.i10),
                    e01 = __ldg(B0 + tB.i01), e11 = __ldg(B0 + tB.i11);
        const float f00 = __ldg(B1 + tB.i00), f10 = __ldg(B1 + tB.i10),
                    f01 = __ldg(B1 + tB.i01), f11 = __ldg(B1 + tB.i11);
        const float h00 = __ldg(B2 + tB.i00), h10 = __ldg(B2 + tB.i10),
                    h01 = __ldg(B2 + tB.i01), h11 = __ldg(B2 + tB.i11);
        const float k00 = __ldg(Bm + tB.i00), k10 = __ldg(Bm + tB.i10),
                    k01 = __ldg(Bm + tB.i01), k11 = __ldg(Bm + tB.i11);

        const float gA0 = tA.w00*a00 + tA.w10*a10 + tA.w01*a01 + tA.w11*a11;
        const float gA1 = tA.w00*b00 + tA.w10*b10 + tA.w01*b01 + tA.w11*b11;
        const float gA2 = tA.w00*c00 + tA.w10*c10 + tA.w01*c01 + tA.w11*c11;
        const float mA  = tA.w00*d00 + tA.w10*d10 + tA.w01*d01 + tA.w11*d11;
        const float gB0 = tB.w00*e00 + tB.w10*e10 + tB.w01*e01 + tB.w11*e11;
        const float gB1 = tB.w00*f00 + tB.w10*f10 + tB.w01*f01 + tB.w11*f11;
        const float gB2 = tB.w00*h00 + tB.w10*h10 + tB.w01*h01 + tB.w11*h11;
        const float mB  = tB.w00*k00 + tB.w10*k10 + tB.w01*k01 + tB.w11*k11;

        stcs(out_gpi + base_gA + pix,          gA0);
        stcs(out_gpi + base_gA + HW + pix,     gA1);
        stcs(out_gpi + base_gA + 2 * HW + pix, gA2);
        stcs(out_mpi + base_mA + pix,          mA);
        stcs(out_gpi + base_gB + pix,          gB0);
        stcs(out_gpi + base_gB + HW + pix,     gB1);
        stcs(out_gpi + base_gB + 2 * HW + pix, gB2);
        stcs(out_mpi + base_mB + pix,          mB);

        gacc0 += gA0 + gB0;
        gacc1 += gA1 + gB1;
        gacc2 += gA2 + gB2;
        macc  += mA  + mB;   // note: same order as ref? see below
    }

    // --- tail (block-uniform) ---
    if (j < nact) {
        const int base_g = (b * NI + s_act_ni[j]) * CC * HW;
        const int base_m = (b * NI + s_act_ni[j]) * HW;
        const TapIW t = tap_iw(fmaf(s_act_t0[j], xf, s_act_bx[j]),
                               fmaf(s_act_t3[j], xf, s_act_by[j]),
                               s_act_coef[j]);
        const float* __restrict__ s0 = g0 + base_g;
        const float* __restrict__ s1 = s0 + HW;
        const float* __restrict__ s2 = s1 + HW;
        const float* __restrict__ sm = m0 + base_m;

        const float a00 = __ldg(s0 + t.i00), a10 = __ldg(s0 + t.i10),
                    a01 = __ldg(s0 + t.i01), a11 = __ldg(s0 + t.i11);
        const float b00 = __ldg(s1 + t.i00), b10 = __ldg(s1 + t.i10),
                    b01 = __ldg(s1 + t.i01), b11 = __ldg(s1 + t.i11);
        const float c00 = __ldg(s2 + t.i00), c10 = __ldg(s2 + t.i10),
                    c01 = __ldg(s2 + t.i01), c11 = __ldg(s2 + t.i11);
        const float d00 = __ldg(sm + t.i00), d10 = __ldg(sm + t.i10),
                    d01 = __ldg(sm + t.i01), d11 = __ldg(sm + t.i11);

        const float g0v = t.w00*a00 + t.w10*a10 + t.w01*a01 + t.w11*a11;
        const float g1v = t.w00*b00 + t.w10*b10 + t.w01*b01 + t.w11*b11;
        const float g2v = t.w00*c00 + t.w10*c10 + t.w01*c01 + t.w11*c11;
        const float mv  = t.w00*d00 + t.w10*d10 + t.w01*d01 + t.w11*d11;

        stcs(out_gpi + base_g + pix,          g0v);
        stcs(out_gpi + base_g + HW + pix,     g1v);
        stcs(out_gpi + base_g + 2 * HW + pix, g2v);
        stcs(out_mpi + base_m + pix,          mv);

        gacc0 += g0v; gacc1 += g1v; gacc2 += g2v; macc += mv;
    }

    // --- reductions + composite (streaming stores) ---
    const int bg = b * CC * HW + pix;
    stcs(out_gmid + bg,          gacc0);
    stcs(out_gmid + bg + HW,     gacc1);
    stcs(out_gmid + bg + 2 * HW, gacc2);
    stcs(out_mmid + b * HW + pix, fminf(fmaxf(macc, 0.0f), 1.0f));
    stcs(out_ibas + bg,          __ldg(i_bg + bg)          + gacc0);
    stcs(out_ibas + bg + HW,     __ldg(i_bg + bg + HW)     + gacc1);
    stcs(out_ibas + bg + 2 * HW, __ldg(i_bg + bg + 2 * HW) + gacc2);
}

extern "C" void kernel_launch(void* const* d_in, const int* in_sizes, int n_in,
                              void* d_out, int out_size) {
    const float* g0          = (const float*)d_in[0];
    const float* m0          = (const float*)d_in[1];
    const float* mode_logits = (const float*)d_in[2];
    const float* tp          = (const float*)d_in[3];
    const float* alpha       = (const float*)d_in[4];
    const float* inst_valid  = (const float*)d_in[5];
    const float* i_bg        = (const float*)d_in[6];
    float* out = (float*)d_out;

    const int B = in_sizes[0] / (NI * CC * HW);

    dim3 grid(B * HH);
    dim3 block(WW);
    warp_renderer_kernel<<<grid, block>>>(g0, m0, mode_logits, tp, alpha,
                                          inst_valid, i_bg, out, B);
}

// round 14
// speedup vs baseline: 1.0349x; 1.0349x over previous
#include <cuda_runtime.h>

#define HH 256
#define WW 256
#define NI 16
#define CC 3
#define HW (HH * WW)

__device__ __forceinline__ void stcs(float* p, float v) {
#if __CUDA_ARCH__ >= 800
    __stcs(p, v);
#else
    *p = v;
#endif
}

__device__ __forceinline__ void stcs4(float* p, float4 v) {
#if __CUDA_ARCH__ >= 800
    __stcs((float4*)p, v);
#else
    *(float4*)p = v;
#endif
}

// grid: blockIdx.x = (b*256 + y)*2 + xtile ; block = 128 threads (half row)
__global__ __launch_bounds__(128, 12)
void warp_renderer_kernel(
    const float* __restrict__ g0,           // [B,NI,C,H,W]
    const float* __restrict__ m0,           // [B,NI,1,H,W]
    const float* __restrict__ mode_logits,  // [B,NI,5]
    const float* __restrict__ tp,           // [B,NI,6]
    const float* __restrict__ alpha,        // [B,NI,1]
    const float* __restrict__ inst_valid,   // [B,NI]
    const float* __restrict__ i_bg,         // [B,C,H,W]
    float* __restrict__ out,
    int B)
{
    __shared__ int   s_nact, s_ninact;
    __shared__ int   s_act_ni[NI];
    __shared__ float s_act_coef[NI];
    __shared__ float s_act_t0[NI], s_act_t3[NI];
    __shared__ float s_act_bx[NI], s_act_by[NI];
    __shared__ int   s_inact_ni[NI];

    const int b     = blockIdx.x >> 9;
    const int y     = (blockIdx.x >> 1) & 255;
    const int xtile = blockIdx.x & 1;

    // --- per-instance precompute + active compaction (lanes 0..15 of warp 0) ---
    if (threadIdx.x < NI) {
        const int lane = threadIdx.x;
        const int inst = b * NI + lane;
        const float* L = mode_logits + inst * 5;
        int mode = 0;
        float best = L[0];
        #pragma unroll
        for (int k = 1; k < 5; ++k) {
            float v = L[k];
            if (v > best) { best = v; mode = k; }  // first-max argmax
        }
        float coef;
        if (mode == 0 || mode == 2 || mode == 4) coef = 1.0f;       // static-like
        else if (mode == 3)                      coef = alpha[inst]; // blink
        else                                     coef = 0.0f;        // mode 1
        coef *= inst_valid[inst];

        const bool active = (coef != 0.0f);
        const unsigned mask = __ballot_sync(0x0000FFFFu, active);
        const unsigned lower = (1u << lane) - 1u;

        if (active) {
            const int pos = __popc(mask & lower);
            const float t0 = tp[inst * 6 + 0];
            const float t1 = tp[inst * 6 + 1];
            const float t2 = tp[inst * 6 + 2];
            const float t3 = tp[inst * 6 + 3];
            const float t4 = tp[inst * 6 + 4];
            const float t5 = tp[inst * 6 + 5];
            const float ys = (2.0f * (float)y + 1.0f) * (1.0f / (float)HH) - 1.0f;
            // ix = t0*x + bx ; iy = t3*x + by   (full chain folded)
            const float bx = 128.0f * (t1 * ys + t2) + 127.5f + 0.5f * t0 - 128.0f * t0;
            const float by = 128.0f * (t4 * ys + t5) + 127.5f + 0.5f * t3 - 128.0f * t3;
            s_act_ni[pos]   = lane;
            s_act_coef[pos] = coef;
            s_act_t0[pos]   = t0;
            s_act_t3[pos]   = t3;
            s_act_bx[pos]   = bx;
            s_act_by[pos]   = by;
        } else {
            const int pos = __popc((~mask) & 0xFFFFu & lower);
            s_inact_ni[pos] = lane;
        }
        if (lane == 0) {
            s_nact   = __popc(mask);
            s_ninact = NI - __popc(mask);
        }
    }
    __syncthreads();

    const int x   = xtile * 128 + threadIdx.x;
    const int pix = y * WW + x;
    const float xf = (float)x;

    const int n_gpi = B * NI * CC * HW;
    const int n_mpi = B * NI * HW;
    float* __restrict__ out_gpi  = out;
    float* __restrict__ out_mpi  = out + n_gpi;
    float* __restrict__ out_gmid = out + n_gpi + n_mpi;
    float* __restrict__ out_mmid = out_gmid + B * CC * HW;
    float* __restrict__ out_ibas = out_mmid + B * HW;

    // --- zero stores for inactive instances: float4 remap ---
    // 128 threads cover (4 arrays) x (32 float4 segments of the 128-px half row).
    // arr 0..2 -> gpi channel, arr 3 -> mpi. 1 STG.128 per thread per instance.
    {
        const int arr = threadIdx.x >> 5;                 // 0..3
        const int seg = (threadIdx.x & 31) * 4;           // 0,4,...,124
        const int zoff = y * WW + xtile * 128 + seg;      // within one [H,W] image
        const float4 z4 = make_float4(0.f, 0.f, 0.f, 0.f);
        const int ninact = s_ninact;
        for (int k = 0; k < ninact; ++k) {
            const int ni = s_inact_ni[k];
            float* dst = (arr < 3)
                ? (out_gpi + (b * NI + ni) * CC * HW + arr * HW + zoff)
                : (out_mpi + (b * NI + ni) * HW + zoff);
            stcs4(dst, z4);
        }
    }

    float gacc0 = 0.0f, gacc1 = 0.0f, gacc2 = 0.0f, macc = 0.0f;

    // --- hot loop: active instances only ---
    const int nact = s_nact;
    for (int j = 0; j < nact; ++j) {
        const int   ni   = s_act_ni[j];
        const float coef = s_act_coef[j];
        const int base_g = (b * NI + ni) * CC * HW;
        const int base_m = (b * NI + ni) * HW;

        const float ix = fmaf(s_act_t0[j], xf, s_act_bx[j]);
        const float iy = fmaf(s_act_t3[j], xf, s_act_by[j]);

        const int x0 = __float2int_rd(ix);
        const int y0 = __float2int_rd(iy);
        const float wx1 = ix - (float)x0;
        const float wy1 = iy - (float)y0;
        const float wx0 = 1.0f - wx1;
        const float wy0 = 1.0f - wy1;
        const int x1 = x0 + 1, y1 = y0 + 1;

        const bool vx0 = (x0 >= 0) & (x0 < WW);
        const bool vx1 = (x1 >= 0) & (x1 < WW);
        const bool vy0 = (y0 >= 0) & (y0 < HH);
        const bool vy1 = (y1 >= 0) & (y1 < HH);

        const int x0c = min(max(x0, 0), WW - 1);
        const int x1c = min(max(x1, 0), WW - 1);
        const int y0c = min(max(y0, 0), HH - 1);
        const int y1c = min(max(y1, 0), HH - 1);

        const float wy0c = wy0 * coef;
        const float wy1c = wy1 * coef;
        const float w00 = wx0 * wy0c * ((vx0 & vy0) ? 1.0f : 0.0f);
        const float w10 = wx1 * wy0c * ((vx1 & vy0) ? 1.0f : 0.0f);
        const float w01 = wx0 * wy1c * ((vx0 & vy1) ? 1.0f : 0.0f);
        const float w11 = wx1 * wy1c * ((vx1 & vy1) ? 1.0f : 0.0f);

        const int i00 = y0c * WW + x0c;
        const int i10 = y0c * WW + x1c;
        const int i01 = y1c * WW + x0c;
        const int i11 = y1c * WW + x1c;

        const float* __restrict__ s0 = g0 + base_g;
        const float* __restrict__ s1 = s0 + HW;
        const float* __restrict__ s2 = s1 + HW;
        const float* __restrict__ sm = m0 + base_m;

        // 16 independent loads in flight
        const float a00 = __ldg(s0 + i00), a10 = __ldg(s0 + i10),
                    a01 = __ldg(s0 + i01), a11 = __ldg(s0 + i11);
        const float b00 = __ldg(s1 + i00), b10 = __ldg(s1 + i10),
                    b01 = __ldg(s1 + i01), b11 = __ldg(s1 + i11);
        const float c00 = __ldg(s2 + i00), c10 = __ldg(s2 + i10),
                    c01 = __ldg(s2 + i01), c11 = __ldg(s2 + i11);
        const float d00 = __ldg(sm + i00), d10 = __ldg(sm + i10),
                    d01 = __ldg(sm + i01), d11 = __ldg(sm + i11);

        const float g0v = w00 * a00 + w10 * a10 + w01 * a01 + w11 * a11;
        const float g1v = w00 * b00 + w10 * b10 + w01 * b01 + w11 * b11;
        const float g2v = w00 * c00 + w10 * c10 + w01 * c01 + w11 * c11;
        const float mv  = w00 * d00 + w10 * d10 + w01 * d01 + w11 * d11;

        stcs(out_gpi + base_g + pix,          g0v);
        stcs(out_gpi + base_g + HW + pix,     g1v);
        stcs(out_gpi + base_g + 2 * HW + pix, g2v);
        stcs(out_mpi + base_m + pix,          mv);

        gacc0 += g0v; gacc1 += g1v; gacc2 += g2v; macc += mv;
    }

    // --- reductions + composite (streaming stores) ---
    const int bg = b * CC * HW + pix;
    stcs(out_gmid + bg,          gacc0);
    stcs(out_gmid + bg + HW,     gacc1);
    stcs(out_gmid + bg + 2 * HW, gacc2);
    stcs(out_mmid + b * HW + pix, fminf(fmaxf(macc, 0.0f), 1.0f));
    stcs(out_ibas + bg,          __ldg(i_bg + bg)          + gacc0);
    stcs(out_ibas + bg + HW,     __ldg(i_bg + bg + HW)     + gacc1);
    stcs(out_ibas + bg + 2 * HW, __ldg(i_bg + bg + 2 * HW) + gacc2);
}

extern "C" void kernel_launch(void* const* d_in, const int* in_sizes, int n_in,
                              void* d_out, int out_size) {
    const float* g0          = (const float*)d_in[0];
    const float* m0          = (const float*)d_in[1];
    const float* mode_logits = (const float*)d_in[2];
    const float* tp          = (const float*)d_in[3];
    const float* alpha       = (const float*)d_in[4];
    const float* inst_valid  = (const float*)d_in[5];
    const float* i_bg        = (const float*)d_in[6];
    float* out = (float*)d_out;

    const int B = in_sizes[0] / (NI * CC * HW);

    dim3 grid(B * HH * 2);   // (b*256 + y)*2 + xtile
    dim3 block(128);
    warp_renderer_kernel<<<grid, block>>>(g0, m0, mode_logits, tp, alpha,
                                          inst_valid, i_bg, out, B);
}

// round 16
// speedup vs baseline: 1.1533x; 1.1144x over previous
#include <cuda_runtime.h>

#define HH 256
#define WW 256
#define NI 16
#define CC 3
#define HW (HH * WW)

__device__ __forceinline__ void stcs(float* p, float v) {
#if __CUDA_ARCH__ >= 800
    __stcs(p, v);
#else
    *p = v;
#endif
}

__device__ __forceinline__ void stcs4(float* p, float4 v) {
#if __CUDA_ARCH__ >= 800
    __stcs((float4*)p, v);
#else
    *(float4*)p = v;
#endif
}

// grid: blockIdx.x = b*H + y ; block = 256 threads (one full row)
__global__ __launch_bounds__(256, 7)
void warp_renderer_kernel(
    const float* __restrict__ g0,           // [B,NI,C,H,W]
    const float* __restrict__ m0,           // [B,NI,1,H,W]
    const float* __restrict__ mode_logits,  // [B,NI,5]
    const float* __restrict__ tp,           // [B,NI,6]
    const float* __restrict__ alpha,        // [B,NI,1]
    const float* __restrict__ inst_valid,   // [B,NI]
    const float* __restrict__ i_bg,         // [B,C,H,W]
    float* __restrict__ out,
    int B)
{
    __shared__ int   s_nact, s_ninact;
    __shared__ int   s_act_ni[NI];
    __shared__ float s_act_coef[NI];
    __shared__ float s_act_t0[NI], s_act_t3[NI];
    __shared__ float s_act_bx[NI], s_act_by[NI];
    __shared__ int   s_inact_ni[NI];

    const int b = blockIdx.x >> 8;        // blockIdx.x = b*H + y
    const int y = blockIdx.x & 255;
    const int x = threadIdx.x;

    // --- per-instance precompute + active compaction (lanes 0..15 of warp 0) ---
    if (threadIdx.x < NI) {
        const int lane = threadIdx.x;
        const int inst = b * NI + lane;
        const float* L = mode_logits + inst * 5;
        int mode = 0;
        float best = L[0];
        #pragma unroll
        for (int k = 1; k < 5; ++k) {
            float v = L[k];
            if (v > best) { best = v; mode = k; }  // first-max argmax
        }
        float coef;
        if (mode == 0 || mode == 2 || mode == 4) coef = 1.0f;       // static-like
        else if (mode == 3)                      coef = alpha[inst]; // blink
        else                                     coef = 0.0f;        // mode 1
        coef *= inst_valid[inst];

        const bool active = (coef != 0.0f);
        const unsigned mask = __ballot_sync(0x0000FFFFu, active);
        const unsigned lower = (1u << lane) - 1u;

        if (active) {
            const int pos = __popc(mask & lower);
            const float t0 = tp[inst * 6 + 0];
            const float t1 = tp[inst * 6 + 1];
            const float t2 = tp[inst * 6 + 2];
            const float t3 = tp[inst * 6 + 3];
            const float t4 = tp[inst * 6 + 4];
            const float t5 = tp[inst * 6 + 5];
            const float ys = (2.0f * (float)y + 1.0f) * (1.0f / (float)HH) - 1.0f;
            // ix = t0*x + bx ; iy = t3*x + by   (full chain folded)
            const float bx = 128.0f * (t1 * ys + t2) + 127.5f + 0.5f * t0 - 128.0f * t0;
            const float by = 128.0f * (t4 * ys + t5) + 127.5f + 0.5f * t3 - 128.0f * t3;
            s_act_ni[pos]   = lane;
            s_act_coef[pos] = coef;
            s_act_t0[pos]   = t0;
            s_act_t3[pos]   = t3;
            s_act_bx[pos]   = bx;
            s_act_by[pos]   = by;
        } else {
            const int pos = __popc((~mask) & 0xFFFFu & lower);
            s_inact_ni[pos] = lane;
        }
        if (lane == 0) {
            s_nact   = __popc(mask);
            s_ninact = NI - __popc(mask);
        }
    }
    __syncthreads();

    const int pix = y * WW + x;
    const float xf = (float)x;

    const int n_gpi = B * NI * CC * HW;
    const int n_mpi = B * NI * HW;
    float* __restrict__ out_gpi  = out;
    float* __restrict__ out_mpi  = out + n_gpi;
    float* __restrict__ out_gmid = out + n_gpi + n_mpi;
    float* __restrict__ out_mmid = out_gmid + B * CC * HW;
    float* __restrict__ out_ibas = out_mmid + B * HW;

    // --- zero stores for inactive instances: float4 remap ---
    // 256 threads cover (4 arrays) x (64 float4 segments of the 256-px row).
    // arr 0..2 -> gpi channel, arr 3 -> mpi. 1 STG.128 per thread per instance.
    {
        const int arr  = threadIdx.x >> 6;            // 0..3
        const int seg  = (threadIdx.x & 63) * 4;      // 0,4,...,252
        const int zoff = y * WW + seg;                // within one [H,W] image
        const float4 z4 = make_float4(0.f, 0.f, 0.f, 0.f);
        const int ninact = s_ninact;
        for (int k = 0; k < ninact; ++k) {
            const int ni = s_inact_ni[k];
            float* dst = (arr < 3)
                ? (out_gpi + (b * NI + ni) * CC * HW + arr * HW + zoff)
                : (out_mpi + (b * NI + ni) * HW + zoff);
            stcs4(dst, z4);
        }
    }

    float gacc0 = 0.0f, gacc1 = 0.0f, gacc2 = 0.0f, macc = 0.0f;

    // --- hot loop: active instances only ---
    const int nact = s_nact;
    for (int j = 0; j < nact; ++j) {
        const int   ni   = s_act_ni[j];
        const float coef = s_act_coef[j];
        const int base_g = (b * NI + ni) * CC * HW;
        const int base_m = (b * NI + ni) * HW;

        const float ix = fmaf(s_act_t0[j], xf, s_act_bx[j]);
        const float iy = fmaf(s_act_t3[j], xf, s_act_by[j]);

        const int x0 = __float2int_rd(ix);
        const int y0 = __float2int_rd(iy);
        const float wx1 = ix - (float)x0;
        const float wy1 = iy - (float)y0;
        const float wx0 = 1.0f - wx1;
        const float wy0 = 1.0f - wy1;
        const int x1 = x0 + 1, y1 = y0 + 1;

        const bool vx0 = (x0 >= 0) & (x0 < WW);
        const bool vx1 = (x1 >= 0) & (x1 < WW);
        const bool vy0 = (y0 >= 0) & (y0 < HH);
        const bool vy1 = (y1 >= 0) & (y1 < HH);

        const int x0c = min(max(x0, 0), WW - 1);
        const int x1c = min(max(x1, 0), WW - 1);
        const int y0c = min(max(y0, 0), HH - 1);
        const int y1c = min(max(y1, 0), HH - 1);

        const float wy0c = wy0 * coef;
        const float wy1c = wy1 * coef;
        const float w00 = wx0 * wy0c * ((vx0 & vy0) ? 1.0f : 0.0f);
        const float w10 = wx1 * wy0c * ((vx1 & vy0) ? 1.0f : 0.0f);
        const float w01 = wx0 * wy1c * ((vx0 & vy1) ? 1.0f : 0.0f);
        const float w11 = wx1 * wy1c * ((vx1 & vy1) ? 1.0f : 0.0f);

        const int i00 = y0c * WW + x0c;
        const int i10 = y0c * WW + x1c;
        const int i01 = y1c * WW + x0c;
        const int i11 = y1c * WW + x1c;

        const float* __restrict__ s0 = g0 + base_g;
        const float* __restrict__ s1 = s0 + HW;
        const float* __restrict__ s2 = s1 + HW;
        const float* __restrict__ sm = m0 + base_m;

        // 16 independent loads in flight
        const float a00 = __ldg(s0 + i00), a10 = __ldg(s0 + i10),
                    a01 = __ldg(s0 + i01), a11 = __ldg(s0 + i11);
        const float b00 = __ldg(s1 + i00), b10 = __ldg(s1 + i10),
                    b01 = __ldg(s1 + i01), b11 = __ldg(s1 + i11);
        const float c00 = __ldg(s2 + i00), c10 = __ldg(s2 + i10),
                    c01 = __ldg(s2 + i01), c11 = __ldg(s2 + i11);
        const float d00 = __ldg(sm + i00), d10 = __ldg(sm + i10),
                    d01 = __ldg(sm + i01), d11 = __ldg(sm + i11);

        const float g0v = w00 * a00 + w10 * a10 + w01 * a01 + w11 * a11;
        const float g1v = w00 * b00 + w10 * b10 + w01 * b01 + w11 * b11;
        const float g2v = w00 * c00 + w10 * c10 + w01 * c01 + w11 * c11;
        const float mv  = w00 * d00 + w10 * d10 + w01 * d01 + w11 * d11;

        stcs(out_gpi + base_g + pix,          g0v);
        stcs(out_gpi + base_g + HW + pix,     g1v);
        stcs(out_gpi + base_g + 2 * HW + pix, g2v);
        stcs(out_mpi + base_m + pix,          mv);

        gacc0 += g0v; gacc1 += g1v; gacc2 += g2v; macc += mv;
    }

    // --- reductions + composite (streaming stores) ---
    const int bg = b * CC * HW + pix;
    stcs(out_gmid + bg,          gacc0);
    stcs(out_gmid + bg + HW,     gacc1);
    stcs(out_gmid + bg + 2 * HW, gacc2);
    stcs(out_mmid + b * HW + pix, fminf(fmaxf(macc, 0.0f), 1.0f));
    stcs(out_ibas + bg,          __ldg(i_bg + bg)          + gacc0);
    stcs(out_ibas + bg + HW,     __ldg(i_bg + bg + HW)     + gacc1);
    stcs(out_ibas + bg + 2 * HW, __ldg(i_bg + bg + 2 * HW) + gacc2);
}

extern "C" void kernel_launch(void* const* d_in, const int* in_sizes, int n_in,
                              void* d_out, int out_size) {
    const float* g0          = (const float*)d_in[0];
    const float* m0          = (const float*)d_in[1];
    const float* mode_logits = (const float*)d_in[2];
    const float* tp          = (const float*)d_in[3];
    const float* alpha       = (const float*)d_in[4];
    const float* inst_valid  = (const float*)d_in[5];
    const float* i_bg        = (const float*)d_in[6];
    float* out = (float*)d_out;

    const int B = in_sizes[0] / (NI * CC * HW);

    dim3 grid(B * HH);
    dim3 block(WW);
    warp_renderer_kernel<<<grid, block>>>(g0, m0, mode_logits, tp, alpha,
                                          inst_valid, i_bg, out, B);
}